// round 3
// baseline (speedup 1.0000x reference)
#include <cuda_runtime.h>
#include <cuda_bf16.h>
#include <math_constants.h>

#define N_NODES 50000
#define N_EDGES 800000
#define D_IN 128
#define D_H 128
#define D_OUT 32

// ---------------- scratch (device globals; no allocation allowed) ----------------
__device__ int   g_cnt[N_NODES];
__device__ int   g_row_ptr[N_NODES + 1];
__device__ int   g_fill[N_NODES];
__device__ int   g_col[N_EDGES];
__device__ float g_agg[(size_t)N_NODES * D_H];
__device__ float g_h[(size_t)N_NODES * D_H];
__device__ float g_B1[256 * D_H];    // prepacked [K=256, N=128]
__device__ float g_B2[256 * D_OUT];  // prepacked [K=256, N=32]
__device__ float g_colsum[D_H];
__device__ float g_colsumsq[D_H];
__device__ float g_scale[D_H];
__device__ float g_shift[D_H];

// ---------------- CSR build ----------------
__global__ void zero_kernel() {
    int i = blockIdx.x * blockDim.x + threadIdx.x;
    if (i < N_NODES) g_cnt[i] = 0;
    if (i < D_H) { g_colsum[i] = 0.f; g_colsumsq[i] = 0.f; }
}

__global__ void hist_kernel(const int* __restrict__ dst, int E) {
    int e = blockIdx.x * blockDim.x + threadIdx.x;
    if (e < E) atomicAdd(&g_cnt[dst[e]], 1);
}

// single-block exclusive scan over g_cnt -> g_row_ptr, g_fill
__global__ void scan_kernel(int n) {
    __shared__ int s[1024];
    __shared__ int carry;
    int t = threadIdx.x;
    if (t == 0) { carry = 0; g_row_ptr[0] = 0; }
    __syncthreads();
    for (int base = 0; base < n; base += 1024) {
        int i = base + t;
        int v = (i < n) ? g_cnt[i] : 0;
        s[t] = v;
        __syncthreads();
        #pragma unroll
        for (int d = 1; d < 1024; d <<= 1) {
            int u = (t >= d) ? s[t - d] : 0;
            __syncthreads();
            s[t] += u;
            __syncthreads();
        }
        int incl = s[t] + carry;
        if (i < n) {
            g_row_ptr[i + 1] = incl;
            g_fill[i] = incl - v;  // exclusive prefix = bucket start
        }
        __syncthreads();
        if (t == 1023) carry = incl;
        __syncthreads();
    }
}

__global__ void scatter_kernel(const int* __restrict__ src, const int* __restrict__ dst, int E) {
    int e = blockIdx.x * blockDim.x + threadIdx.x;
    if (e < E) {
        int d = dst[e];
        int pos = atomicAdd(&g_fill[d], 1);
        g_col[pos] = src[e];
    }
}

// ---------------- scatter-max aggregation: one warp per node ----------------
__global__ void agg_max_kernel(const float* __restrict__ X, float* __restrict__ AGG, int nNodes) {
    int warp = (blockIdx.x * blockDim.x + threadIdx.x) >> 5;
    int lane = threadIdx.x & 31;
    if (warp >= nNodes) return;
    int s = g_row_ptr[warp];
    int e = g_row_ptr[warp + 1];
    float4 m = make_float4(-CUDART_INF_F, -CUDART_INF_F, -CUDART_INF_F, -CUDART_INF_F);
    const float4* X4 = reinterpret_cast<const float4*>(X);
    for (int i = s; i < e; i++) {
        int src = __ldg(&g_col[i]);
        float4 v = __ldg(&X4[(size_t)src * 32 + lane]);
        m.x = fmaxf(m.x, v.x); m.y = fmaxf(m.y, v.y);
        m.z = fmaxf(m.z, v.z); m.w = fmaxf(m.w, v.w);
    }
    if (s == e) m = make_float4(0.f, 0.f, 0.f, 0.f);  // isolated node -> 0
    reinterpret_cast<float4*>(AGG)[(size_t)warp * 32 + lane] = m;
}

// ---------------- weight prepack: B[k*N+j] = (k<128 ? Wl[j,k] : Wr[j,k-128]) ----------------
__global__ void prepack_kernel(const float* __restrict__ Wl, const float* __restrict__ Wr,
                               float* __restrict__ B, int N) {
    int idx = blockIdx.x * blockDim.x + threadIdx.x;
    if (idx >= 256 * N) return;
    int k = idx / N, j = idx % N;
    B[idx] = (k < 128) ? Wl[j * 128 + k] : Wr[j * 128 + (k - 128)];
}

// ---------------- tiled fp32 GEMM over concat A = [A0 | A1], K=256 ----------------
template <int BM, int BN, int BK, int TM, int TN>
__launch_bounds__((BM / TM) * (BN / TN))
__global__ void gemm_concat_kernel(const float* __restrict__ A0, const float* __restrict__ A1,
                                   const float* __restrict__ B, const float* __restrict__ bias,
                                   float* __restrict__ C, int M, int N) {
    constexpr int K = 256, K0 = 128;
    constexpr int THREADS = (BM / TM) * (BN / TN);
    __shared__ float As[BK][BM];
    __shared__ float Bs[BK][BN];
    int tid = threadIdx.x;
    int m0 = blockIdx.x * BM;
    int n0 = blockIdx.y * BN;
    int tcol = tid % (BN / TN);
    int trow = tid / (BN / TN);
    float acc[TM][TN];
    #pragma unroll
    for (int i = 0; i < TM; i++)
        #pragma unroll
        for (int j = 0; j < TN; j++) acc[i][j] = 0.f;

    for (int k0 = 0; k0 < K; k0 += BK) {
        // A tile: BM x BK, float4 along K
        #pragma unroll
        for (int idx = tid; idx < BM * BK / 4; idx += THREADS) {
            int m  = idx / (BK / 4);
            int kq = (idx % (BK / 4)) * 4;
            int row = m0 + m;
            int k = k0 + kq;
            float4 v = make_float4(0.f, 0.f, 0.f, 0.f);
            if (row < M) {
                const float* src = (k < K0) ? (A0 + (size_t)row * K0 + k)
                                            : (A1 + (size_t)row * K0 + (k - K0));
                v = *reinterpret_cast<const float4*>(src);
            }
            As[kq + 0][m] = v.x; As[kq + 1][m] = v.y;
            As[kq + 2][m] = v.z; As[kq + 3][m] = v.w;
        }
        // B tile: BK x BN
        #pragma unroll
        for (int idx = tid; idx < BK * BN / 4; idx += THREADS) {
            int kr = idx / (BN / 4);
            int nq = (idx % (BN / 4)) * 4;
            float4 v = *reinterpret_cast<const float4*>(B + (size_t)(k0 + kr) * N + n0 + nq);
            *reinterpret_cast<float4*>(&Bs[kr][nq]) = v;
        }
        __syncthreads();
        #pragma unroll
        for (int kk = 0; kk < BK; kk++) {
            float ra[TM], rb[TN];
            #pragma unroll
            for (int i = 0; i < TM; i++) ra[i] = As[kk][trow * TM + i];
            #pragma unroll
            for (int j = 0; j < TN; j++) rb[j] = Bs[kk][tcol * TN + j];
            #pragma unroll
            for (int i = 0; i < TM; i++)
                #pragma unroll
                for (int j = 0; j < TN; j++) acc[i][j] += ra[i] * rb[j];
        }
        __syncthreads();
    }
    #pragma unroll
    for (int i = 0; i < TM; i++) {
        int row = m0 + trow * TM + i;
        if (row >= M) continue;
        #pragma unroll
        for (int j = 0; j < TN; j++) {
            int cn = n0 + tcol * TN + j;
            C[(size_t)row * N + cn] = acc[i][j] + bias[cn];
        }
    }
}

// ---------------- batch norm ----------------
__global__ void colstats_kernel(const float* __restrict__ H, int M) {
    int j = threadIdx.x;  // 128 threads = 128 columns
    float s = 0.f, s2 = 0.f;
    for (int i = blockIdx.x; i < M; i += gridDim.x) {
        float v = H[(size_t)i * D_H + j];
        s += v; s2 += v * v;
    }
    atomicAdd(&g_colsum[j], s);
    atomicAdd(&g_colsumsq[j], s2);
}

__global__ void bn_finalize_kernel(float invM, const float* __restrict__ gamma,
                                   const float* __restrict__ beta) {
    int j = threadIdx.x;
    float mean = g_colsum[j] * invM;
    float var = g_colsumsq[j] * invM - mean * mean;
    float sc = gamma[j] * rsqrtf(var + 1e-5f);
    g_scale[j] = sc;
    g_shift[j] = beta[j] - mean * sc;
}

__global__ void bn_apply_relu_kernel(float* __restrict__ H, int total) {
    int idx = blockIdx.x * blockDim.x + threadIdx.x;
    if (idx < total) {
        int j = idx & (D_H - 1);
        float v = H[idx];
        H[idx] = fmaxf(v * g_scale[j] + g_shift[j], 0.f);
    }
}

// ---------------- launch ----------------
extern "C" void kernel_launch(void* const* d_in, const int* in_sizes, int n_in,
                              void* d_out, int out_size) {
    const float* x     = (const float*)d_in[0];
    const int*   ei    = (const int*)d_in[1];
    const float* Wl1   = (const float*)d_in[2];
    const float* bl1   = (const float*)d_in[3];
    const float* Wr1   = (const float*)d_in[4];
    const float* gamma = (const float*)d_in[5];
    const float* beta  = (const float*)d_in[6];
    const float* Wl2   = (const float*)d_in[7];
    const float* bl2   = (const float*)d_in[8];
    const float* Wr2   = (const float*)d_in[9];
    float* out = (float*)d_out;

    int M = in_sizes[0] / D_IN;       // 50000
    int E = in_sizes[1] / 2;          // 800000
    const int* src = ei;
    const int* dst = ei + E;

    float *p_agg, *p_h, *p_B1, *p_B2;
    cudaGetSymbolAddress((void**)&p_agg, g_agg);
    cudaGetSymbolAddress((void**)&p_h,   g_h);
    cudaGetSymbolAddress((void**)&p_B1,  g_B1);
    cudaGetSymbolAddress((void**)&p_B2,  g_B2);

    // CSR build
    zero_kernel<<<(N_NODES + 255) / 256, 256>>>();
    hist_kernel<<<(E + 255) / 256, 256>>>(dst, E);
    scan_kernel<<<1, 1024>>>(M);
    scatter_kernel<<<(E + 255) / 256, 256>>>(src, dst, E);

    // weight prepack
    prepack_kernel<<<(256 * D_H + 255) / 256, 256>>>(Wl1, Wr1, p_B1, D_H);
    prepack_kernel<<<(256 * D_OUT + 255) / 256, 256>>>(Wl2, Wr2, p_B2, D_OUT);

    // layer 1: agg = scatter_max(x); h = [agg|x] @ B1 + b1
    agg_max_kernel<<<(M * 32 + 255) / 256, 256>>>(x, p_agg, M);
    {
        dim3 grid((M + 127) / 128, D_H / 128);
        gemm_concat_kernel<128, 128, 16, 8, 8><<<grid, 256>>>(p_agg, x, p_B1, bl1, p_h, M, D_H);
    }

    // batch norm + relu (in place on h)
    colstats_kernel<<<256, D_H>>>(p_h, M);
    bn_finalize_kernel<<<1, D_H>>>(1.0f / (float)M, gamma, beta);
    bn_apply_relu_kernel<<<(M * D_H + 255) / 256, 256>>>(p_h, M * D_H);

    // layer 2: agg2 = scatter_max(h); out = [agg2|h] @ B2 + b2
    agg_max_kernel<<<(M * 32 + 255) / 256, 256>>>(p_h, p_agg, M);
    {
        dim3 grid((M + 127) / 128, D_OUT / 32);
        gemm_concat_kernel<128, 32, 16, 8, 4><<<grid, 128>>>(p_agg, p_h, p_B2, bl2, out, M, D_OUT);
    }
}

// round 4
// speedup vs baseline: 1.2283x; 1.2283x over previous
#include <cuda_runtime.h>
#include <cuda_bf16.h>
#include <math_constants.h>

#define N_NODES 50000
#define N_EDGES 800000
#define D_IN 128
#define D_H 128
#define D_OUT 32

// ---------------- scratch (device globals; no allocation allowed) ----------------
__device__ int   g_cnt[N_NODES];
__device__ int   g_row_ptr[N_NODES + 1];
__device__ int   g_rank[N_EDGES];
__device__ int   g_col[N_EDGES];
__device__ float g_agg[(size_t)N_NODES * D_H];
__device__ float g_h[(size_t)N_NODES * D_H];
__device__ float g_B1[256 * D_H];    // prepacked [K=256, N=128]
__device__ float g_B2[256 * D_OUT];  // prepacked [K=256, N=32]
__device__ float g_colsum[D_H];
__device__ float g_colsumsq[D_H];
__device__ float g_scale[D_H];
__device__ float g_shift[D_H];

// ---------------- setup: zero counters/stats + prepack both weight blocks ----------------
// B[k*N+j] = (k<128 ? Wl[j,k] : Wr[j,k-128])
__global__ void setup_kernel(const float* __restrict__ Wl1, const float* __restrict__ Wr1,
                             const float* __restrict__ Wl2, const float* __restrict__ Wr2) {
    int i = blockIdx.x * blockDim.x + threadIdx.x;
    if (i < N_NODES) g_cnt[i] = 0;
    if (i < D_H) { g_colsum[i] = 0.f; g_colsumsq[i] = 0.f; }
    if (i < 256 * D_H) {
        int k = i / D_H, j = i % D_H;
        g_B1[i] = (k < 128) ? Wl1[j * 128 + k] : Wr1[j * 128 + (k - 128)];
    }
    if (i < 256 * D_OUT) {
        int k = i / D_OUT, j = i % D_OUT;
        g_B2[i] = (k < 128) ? Wl2[j * 128 + k] : Wr2[j * 128 + (k - 128)];
    }
}

// ---------------- CSR build ----------------
// histogram + per-edge rank in one pass
__global__ void hist_kernel(const int* __restrict__ dst, int E) {
    int e = blockIdx.x * blockDim.x + threadIdx.x;
    if (e < E) g_rank[e] = atomicAdd(&g_cnt[dst[e]], 1);
}

// fast exclusive scan: serial chunk sums -> 1024-wide Kogge-Stone -> serial writeback
__global__ void scan_kernel(int n) {
    __shared__ int s[1024];
    const int PER = (n + 1023) / 1024;
    int t = threadIdx.x;
    int start = t * PER;
    int end = min(start + PER, n);
    int sum = 0;
    for (int i = start; i < end; i++) sum += g_cnt[i];
    s[t] = sum;
    __syncthreads();
    #pragma unroll
    for (int d = 1; d < 1024; d <<= 1) {
        int u = (t >= d) ? s[t - d] : 0;
        __syncthreads();
        s[t] += u;
        __syncthreads();
    }
    int run = s[t] - sum;  // exclusive prefix of this chunk
    for (int i = start; i < end; i++) {
        int c = g_cnt[i];
        g_row_ptr[i] = run;
        run += c;
    }
    if (t == 1023) g_row_ptr[n] = run;
}

// atomic-free scatter using recorded ranks
__global__ void scatter_kernel(const int* __restrict__ src, const int* __restrict__ dst, int E) {
    int e = blockIdx.x * blockDim.x + threadIdx.x;
    if (e < E) {
        int d = dst[e];
        g_col[g_row_ptr[d] + g_rank[e]] = src[e];
    }
}

// ---------------- scatter-max aggregation: one warp per node ----------------
// XFORM: apply fused BN affine + ReLU to each gathered element before max
template <bool XFORM>
__global__ void agg_max_kernel(const float* __restrict__ X, float* __restrict__ AGG, int nNodes) {
    int warp = (blockIdx.x * blockDim.x + threadIdx.x) >> 5;
    int lane = threadIdx.x & 31;
    if (warp >= nNodes) return;
    int s = g_row_ptr[warp];
    int e = g_row_ptr[warp + 1];
    float4 sc, sh;
    if (XFORM) {
        sc = *reinterpret_cast<const float4*>(&g_scale[lane * 4]);
        sh = *reinterpret_cast<const float4*>(&g_shift[lane * 4]);
    }
    float4 m = make_float4(-CUDART_INF_F, -CUDART_INF_F, -CUDART_INF_F, -CUDART_INF_F);
    const float4* X4 = reinterpret_cast<const float4*>(X);
    #pragma unroll 2
    for (int i = s; i < e; i++) {
        int src = __ldg(&g_col[i]);
        float4 v = __ldg(&X4[(size_t)src * 32 + lane]);
        if (XFORM) {
            v.x = fmaxf(fmaf(v.x, sc.x, sh.x), 0.f);
            v.y = fmaxf(fmaf(v.y, sc.y, sh.y), 0.f);
            v.z = fmaxf(fmaf(v.z, sc.z, sh.z), 0.f);
            v.w = fmaxf(fmaf(v.w, sc.w, sh.w), 0.f);
        }
        m.x = fmaxf(m.x, v.x); m.y = fmaxf(m.y, v.y);
        m.z = fmaxf(m.z, v.z); m.w = fmaxf(m.w, v.w);
    }
    if (s == e) m = make_float4(0.f, 0.f, 0.f, 0.f);  // isolated node -> 0
    reinterpret_cast<float4*>(AGG)[(size_t)warp * 32 + lane] = m;
}

// ---------------- tiled fp32 GEMM over concat A = [A0 | A1], K=256 ----------------
// STATS:     accumulate per-column sum/sumsq of C into g_colsum/g_colsumsq (for BN)
// AFFINE_A1: apply BN affine + ReLU to A1 elements while loading (layer 2 lin_r input)
template <int BM, int BN, int BK, int TM, int TN, bool STATS, bool AFFINE_A1>
__launch_bounds__((BM / TM) * (BN / TN))
__global__ void gemm_concat_kernel(const float* __restrict__ A0, const float* __restrict__ A1,
                                   const float* __restrict__ B, const float* __restrict__ bias,
                                   float* __restrict__ C, int M, int N) {
    constexpr int K = 256, K0 = 128;
    constexpr int THREADS = (BM / TM) * (BN / TN);
    constexpr int ASTRIDE = BM + 4;  // pad to break STS bank conflicts on transpose
    __shared__ float As[BK][ASTRIDE];
    __shared__ float Bs[BK][BN];
    __shared__ float ssum[STATS ? BN : 1];
    __shared__ float ssq[STATS ? BN : 1];
    int tid = threadIdx.x;
    int m0 = blockIdx.x * BM;
    int n0 = blockIdx.y * BN;
    int tcol = tid % (BN / TN);
    int trow = tid / (BN / TN);

    if (STATS) {
        for (int j = tid; j < BN; j += THREADS) { ssum[j] = 0.f; ssq[j] = 0.f; }
    }

    float acc[TM][TN];
    #pragma unroll
    for (int i = 0; i < TM; i++)
        #pragma unroll
        for (int j = 0; j < TN; j++) acc[i][j] = 0.f;

    #pragma unroll 1
    for (int k0 = 0; k0 < K; k0 += BK) {
        // A tile: BM x BK, float4 along K, stored transposed
        #pragma unroll
        for (int idx = tid; idx < BM * BK / 4; idx += THREADS) {
            int m  = idx / (BK / 4);
            int kq = (idx % (BK / 4)) * 4;
            int row = m0 + m;
            int k = k0 + kq;
            float4 v = make_float4(0.f, 0.f, 0.f, 0.f);
            if (row < M) {
                if (k < K0) {
                    v = *reinterpret_cast<const float4*>(A0 + (size_t)row * K0 + k);
                } else {
                    int c = k - K0;
                    v = *reinterpret_cast<const float4*>(A1 + (size_t)row * K0 + c);
                    if (AFFINE_A1) {
                        v.x = fmaxf(fmaf(v.x, g_scale[c + 0], g_shift[c + 0]), 0.f);
                        v.y = fmaxf(fmaf(v.y, g_scale[c + 1], g_shift[c + 1]), 0.f);
                        v.z = fmaxf(fmaf(v.z, g_scale[c + 2], g_shift[c + 2]), 0.f);
                        v.w = fmaxf(fmaf(v.w, g_scale[c + 3], g_shift[c + 3]), 0.f);
                    }
                }
            }
            As[kq + 0][m] = v.x; As[kq + 1][m] = v.y;
            As[kq + 2][m] = v.z; As[kq + 3][m] = v.w;
        }
        // B tile: BK x BN
        #pragma unroll
        for (int idx = tid; idx < BK * BN / 4; idx += THREADS) {
            int kr = idx / (BN / 4);
            int nq = (idx % (BN / 4)) * 4;
            float4 v = *reinterpret_cast<const float4*>(B + (size_t)(k0 + kr) * N + n0 + nq);
            *reinterpret_cast<float4*>(&Bs[kr][nq]) = v;
        }
        __syncthreads();
        #pragma unroll
        for (int kk = 0; kk < BK; kk++) {
            float ra[TM], rb[TN];
            #pragma unroll
            for (int i = 0; i < TM; i += 4) {
                float4 a = *reinterpret_cast<const float4*>(&As[kk][trow * TM + i]);
                ra[i] = a.x; ra[i + 1] = a.y; ra[i + 2] = a.z; ra[i + 3] = a.w;
            }
            #pragma unroll
            for (int j = 0; j < TN; j += 4) {
                float4 b = *reinterpret_cast<const float4*>(&Bs[kk][tcol * TN + j]);
                rb[j] = b.x; rb[j + 1] = b.y; rb[j + 2] = b.z; rb[j + 3] = b.w;
            }
            #pragma unroll
            for (int i = 0; i < TM; i++)
                #pragma unroll
                for (int j = 0; j < TN; j++) acc[i][j] += ra[i] * rb[j];
        }
        __syncthreads();
    }

    float ps[TN], pq[TN];
    if (STATS) {
        #pragma unroll
        for (int j = 0; j < TN; j++) { ps[j] = 0.f; pq[j] = 0.f; }
    }
    #pragma unroll
    for (int i = 0; i < TM; i++) {
        int row = m0 + trow * TM + i;
        if (row >= M) continue;
        #pragma unroll
        for (int j = 0; j < TN; j++) {
            int cn = n0 + tcol * TN + j;
            float v = acc[i][j] + bias[cn];
            C[(size_t)row * N + cn] = v;
            if (STATS) { ps[j] += v; pq[j] += v * v; }
        }
    }
    if (STATS) {
        #pragma unroll
        for (int j = 0; j < TN; j++) {
            atomicAdd(&ssum[tcol * TN + j], ps[j]);
            atomicAdd(&ssq[tcol * TN + j], pq[j]);
        }
        __syncthreads();
        for (int j = tid; j < BN; j += THREADS) {
            atomicAdd(&g_colsum[n0 + j], ssum[j]);
            atomicAdd(&g_colsumsq[n0 + j], ssq[j]);
        }
    }
}

// ---------------- BN finalize: fold mean/var + gamma/beta into scale/shift ----------------
__global__ void bn_finalize_kernel(float invM, const float* __restrict__ gamma,
                                   const float* __restrict__ beta) {
    int j = threadIdx.x;
    float mean = g_colsum[j] * invM;
    float var = g_colsumsq[j] * invM - mean * mean;
    float sc = gamma[j] * rsqrtf(var + 1e-5f);
    g_scale[j] = sc;
    g_shift[j] = beta[j] - mean * sc;
}

// ---------------- launch ----------------
extern "C" void kernel_launch(void* const* d_in, const int* in_sizes, int n_in,
                              void* d_out, int out_size) {
    const float* x     = (const float*)d_in[0];
    const int*   ei    = (const int*)d_in[1];
    const float* Wl1   = (const float*)d_in[2];
    const float* bl1   = (const float*)d_in[3];
    const float* Wr1   = (const float*)d_in[4];
    const float* gamma = (const float*)d_in[5];
    const float* beta  = (const float*)d_in[6];
    const float* Wl2   = (const float*)d_in[7];
    const float* bl2   = (const float*)d_in[8];
    const float* Wr2   = (const float*)d_in[9];
    float* out = (float*)d_out;

    int M = in_sizes[0] / D_IN;       // 50000
    int E = in_sizes[1] / 2;          // 800000
    const int* src = ei;
    const int* dst = ei + E;

    float *p_agg, *p_h, *p_B1, *p_B2;
    cudaGetSymbolAddress((void**)&p_agg, g_agg);
    cudaGetSymbolAddress((void**)&p_h,   g_h);
    cudaGetSymbolAddress((void**)&p_B1,  g_B1);
    cudaGetSymbolAddress((void**)&p_B2,  g_B2);

    // setup: zero counters/stats + prepack weights (one launch)
    setup_kernel<<<(N_NODES + 255) / 256, 256>>>(Wl1, Wr1, Wl2, Wr2);

    // CSR build: hist(+rank) -> fast scan -> atomic-free scatter
    hist_kernel<<<(E + 255) / 256, 256>>>(dst, E);
    scan_kernel<<<1, 1024>>>(M);
    scatter_kernel<<<(E + 255) / 256, 256>>>(src, dst, E);

    // layer 1: agg = scatter_max(x); h = [agg|x] @ B1 + b1  (+ fused BN column stats)
    agg_max_kernel<false><<<(M * 32 + 255) / 256, 256>>>(x, p_agg, M);
    {
        dim3 grid((M + 127) / 128, D_H / 128);
        gemm_concat_kernel<128, 128, 16, 8, 8, true, false>
            <<<grid, 256>>>(p_agg, x, p_B1, bl1, p_h, M, D_H);
    }
    bn_finalize_kernel<<<1, D_H>>>(1.0f / (float)M, gamma, beta);

    // layer 2 (BN affine + ReLU fused into both consumers of h):
    //   agg2 = scatter_max(relu(bn(h)));  out = [agg2 | relu(bn(h))] @ B2 + b2
    agg_max_kernel<true><<<(M * 32 + 255) / 256, 256>>>(p_h, p_agg, M);
    {
        dim3 grid((M + 127) / 128, D_OUT / 32);
        gemm_concat_kernel<128, 32, 16, 8, 4, false, true>
            <<<grid, 128>>>(p_agg, p_h, p_B2, bl2, out, M, D_OUT);
    }
}

// round 6
// speedup vs baseline: 1.4762x; 1.2019x over previous
#include <cuda_runtime.h>
#include <cuda_bf16.h>
#include <math_constants.h>
#include <cstdint>

#define N_NODES 50000
#define N_EDGES 800000
#define D_IN 128
#define D_H 128
#define D_OUT 32

// ---------------- scratch (device globals; no allocation allowed) ----------------
__device__ int   g_cnt[N_NODES];
__device__ int   g_row_ptr[N_NODES + 1];
__device__ int   g_rank[N_EDGES];
__device__ int   g_col[N_EDGES];
__device__ float g_agg[(size_t)N_NODES * D_H];
__device__ float g_h[(size_t)N_NODES * D_H];
__device__ float g_B1t[128 * 256];   // layer-1 weights [N=128][K=256] K-major, tf32-rounded
__device__ float g_B2[256 * D_OUT];  // layer-2 prepacked [K=256, N=32] for SIMT GEMM
__device__ float g_colsum[D_H];
__device__ float g_colsumsq[D_H];
__device__ float g_scale[D_H];
__device__ float g_shift[D_H];

__device__ __forceinline__ float f2tf32(float x) {
    float r;
    asm("cvt.rna.tf32.f32 %0, %1;" : "=f"(r) : "f"(x));
    return r;
}

// ---------------- setup: zero counters/stats + prepack both weight blocks ----------------
__global__ void setup_kernel(const float* __restrict__ Wl1, const float* __restrict__ Wr1,
                             const float* __restrict__ Wl2, const float* __restrict__ Wr2) {
    int i = blockIdx.x * blockDim.x + threadIdx.x;
    if (i < N_NODES) g_cnt[i] = 0;
    if (i < D_H) { g_colsum[i] = 0.f; g_colsumsq[i] = 0.f; }
    if (i < 128 * 256) {  // B1t[n][k], K-major, tf32-rounded (rna)
        int n = i / 256, k = i % 256;
        float v = (k < 128) ? Wl1[n * 128 + k] : Wr1[n * 128 + (k - 128)];
        g_B1t[i] = f2tf32(v);
    }
    if (i < 256 * D_OUT) {  // B2[k][j] for SIMT GEMM2
        int k = i / D_OUT, j = i % D_OUT;
        g_B2[i] = (k < 128) ? Wl2[j * 128 + k] : Wr2[j * 128 + (k - 128)];
    }
}

// ---------------- CSR build ----------------
__global__ void hist_kernel(const int* __restrict__ dst, int E) {
    int e = blockIdx.x * blockDim.x + threadIdx.x;
    if (e < E) g_rank[e] = atomicAdd(&g_cnt[dst[e]], 1);
}

__global__ void scan_kernel(int n) {
    __shared__ int s[1024];
    const int PER = (n + 1023) / 1024;
    int t = threadIdx.x;
    int start = t * PER;
    int end = min(start + PER, n);
    int sum = 0;
    for (int i = start; i < end; i++) sum += g_cnt[i];
    s[t] = sum;
    __syncthreads();
    #pragma unroll
    for (int d = 1; d < 1024; d <<= 1) {
        int u = (t >= d) ? s[t - d] : 0;
        __syncthreads();
        s[t] += u;
        __syncthreads();
    }
    int run = s[t] - sum;
    for (int i = start; i < end; i++) {
        int c = g_cnt[i];
        g_row_ptr[i] = run;
        run += c;
    }
    if (t == 1023) g_row_ptr[n] = run;
}

__global__ void scatter_kernel(const int* __restrict__ src, const int* __restrict__ dst, int E) {
    int e = blockIdx.x * blockDim.x + threadIdx.x;
    if (e < E) {
        int d = dst[e];
        g_col[g_row_ptr[d] + g_rank[e]] = src[e];
    }
}

// ---------------- scatter-max aggregation: one warp per node ----------------
template <bool XFORM>
__global__ void agg_max_kernel(const float* __restrict__ X, float* __restrict__ AGG, int nNodes) {
    int warp = (blockIdx.x * blockDim.x + threadIdx.x) >> 5;
    int lane = threadIdx.x & 31;
    if (warp >= nNodes) return;
    int s = g_row_ptr[warp];
    int e = g_row_ptr[warp + 1];
    float4 sc, sh;
    if (XFORM) {
        sc = *reinterpret_cast<const float4*>(&g_scale[lane * 4]);
        sh = *reinterpret_cast<const float4*>(&g_shift[lane * 4]);
    }
    float4 m = make_float4(-CUDART_INF_F, -CUDART_INF_F, -CUDART_INF_F, -CUDART_INF_F);
    const float4* X4 = reinterpret_cast<const float4*>(X);
    #pragma unroll 2
    for (int i = s; i < e; i++) {
        int src = __ldg(&g_col[i]);
        float4 v = __ldg(&X4[(size_t)src * 32 + lane]);
        if (XFORM) {
            v.x = fmaxf(fmaf(v.x, sc.x, sh.x), 0.f);
            v.y = fmaxf(fmaf(v.y, sc.y, sh.y), 0.f);
            v.z = fmaxf(fmaf(v.z, sc.z, sh.z), 0.f);
            v.w = fmaxf(fmaf(v.w, sc.w, sh.w), 0.f);
        }
        m.x = fmaxf(m.x, v.x); m.y = fmaxf(m.y, v.y);
        m.z = fmaxf(m.z, v.z); m.w = fmaxf(m.w, v.w);
    }
    if (s == e) m = make_float4(0.f, 0.f, 0.f, 0.f);
    reinterpret_cast<float4*>(AGG)[(size_t)warp * 32 + lane] = m;
}

// ---------------- layer-1 GEMM via mma.sync tf32 (sm_80+ PTX, no 'a' features) ----------------
// C[M,128] = [A0 | A1] @ B1t^T + bias, with fused BN column stats on C.
// CTA tile 128x128, 8 warps in 4(M) x 2(N), warp tile 32x64, m16n8k8 tf32.
#define G1_BSTRIDE 260          // 256 + 4 pad (words) -> conflict-free b-frag LDS
#define G1_ASTRIDE 68           // 64 + 4 pad
#define G1_SMEM_WORDS (128 * G1_BSTRIDE + 128 * G1_ASTRIDE + 256)
#define G1_SMEM_BYTES (G1_SMEM_WORDS * 4)

__device__ __forceinline__ void mma_tf32(float* d, const uint32_t* a, const uint32_t* b) {
    asm volatile(
        "mma.sync.aligned.m16n8k8.row.col.f32.tf32.tf32.f32 "
        "{%0,%1,%2,%3}, {%4,%5,%6,%7}, {%8,%9}, {%0,%1,%2,%3};"
        : "+f"(d[0]), "+f"(d[1]), "+f"(d[2]), "+f"(d[3])
        : "r"(a[0]), "r"(a[1]), "r"(a[2]), "r"(a[3]), "r"(b[0]), "r"(b[1]));
}

__global__ __launch_bounds__(256, 1)
void gemm1_mma_kernel(const float* __restrict__ A0, const float* __restrict__ A1,
                      const float* __restrict__ Bt, const float* __restrict__ bias,
                      float* __restrict__ C, int M) {
    extern __shared__ float sm[];
    float* Bs   = sm;                                   // [128][260]
    float* As   = sm + 128 * G1_BSTRIDE;                // [128][68]
    float* ssum = As + 128 * G1_ASTRIDE;                // [128]
    float* ssq  = ssum + 128;                           // [128]

    int tid = threadIdx.x;
    int lane = tid & 31;
    int wid = tid >> 5;
    int warpM = wid & 3;         // 0..3 -> 32-row slabs
    int warpN = wid >> 2;        // 0..1 -> 64-col slabs
    int g = lane >> 2;           // group id 0..7
    int tig = lane & 3;          // thread-in-group 0..3
    int m0 = blockIdx.x * 128;

    if (tid < 128) { ssum[tid] = 0.f; ssq[tid] = 0.f; }

    // ---- load full B tile [128 n][256 k] (already tf32-rounded) ----
    const float4* Bt4 = reinterpret_cast<const float4*>(Bt);
    #pragma unroll 8
    for (int idx = tid; idx < 128 * 64; idx += 256) {
        int n = idx >> 6, k4 = idx & 63;
        float4 v = __ldg(&Bt4[n * 64 + k4]);
        *reinterpret_cast<float4*>(&Bs[n * G1_BSTRIDE + k4 * 4]) = v;
    }

    float acc[2][8][4];
    #pragma unroll
    for (int mi = 0; mi < 2; mi++)
        #pragma unroll
        for (int ni = 0; ni < 8; ni++)
            #pragma unroll
            for (int q = 0; q < 4; q++) acc[mi][ni][q] = 0.f;

    // ---- register-staged A pipeline: stage chunk, STS+cvt, prefetch next, compute ----
    // chunk kc covers K cols [kc*64, kc*64+64); kc<2 from A0, else A1
    float4 stage[8];
    {
        const float4* S4 = reinterpret_cast<const float4*>(A0);
        #pragma unroll
        for (int j = 0; j < 8; j++) {
            int i = tid + 256 * j;          // i in [0, 2048): r = i>>4, c4 = i&15
            int r = i >> 4, c4 = i & 15;
            int row = m0 + r;
            stage[j] = (row < M) ? __ldg(&S4[(size_t)row * 32 + c4])
                                 : make_float4(0.f, 0.f, 0.f, 0.f);
        }
    }

    #pragma unroll 1
    for (int kc = 0; kc < 4; kc++) {
        __syncthreads();   // As free (previous compute done) / B ready on first iter
        #pragma unroll
        for (int j = 0; j < 8; j++) {
            int i = tid + 256 * j;
            int r = i >> 4, c4 = i & 15;
            float4 v = stage[j];
            v.x = f2tf32(v.x); v.y = f2tf32(v.y); v.z = f2tf32(v.z); v.w = f2tf32(v.w);
            *reinterpret_cast<float4*>(&As[r * G1_ASTRIDE + c4 * 4]) = v;
        }
        if (kc < 3) {  // prefetch next chunk while this one computes
            int nc = kc + 1;
            const float4* S4 = reinterpret_cast<const float4*>(nc < 2 ? A0 : A1);
            int cbase = (nc & 1) * 16;  // col offset in float4 units within 128-col source
            #pragma unroll
            for (int j = 0; j < 8; j++) {
                int i = tid + 256 * j;
                int r = i >> 4, c4 = i & 15;
                int row = m0 + r;
                stage[j] = (row < M) ? __ldg(&S4[(size_t)row * 32 + cbase + c4])
                                     : make_float4(0.f, 0.f, 0.f, 0.f);
            }
        }
        __syncthreads();   // As visible

        const float* Bkc = Bs + kc * 64;
        #pragma unroll
        for (int ks = 0; ks < 8; ks++) {
            int k = ks * 8;
            uint32_t afr[2][4];
            #pragma unroll
            for (int mi = 0; mi < 2; mi++) {
                int r = warpM * 32 + mi * 16 + g;
                afr[mi][0] = __float_as_uint(As[r * G1_ASTRIDE + k + tig]);
                afr[mi][1] = __float_as_uint(As[(r + 8) * G1_ASTRIDE + k + tig]);
                afr[mi][2] = __float_as_uint(As[r * G1_ASTRIDE + k + tig + 4]);
                afr[mi][3] = __float_as_uint(As[(r + 8) * G1_ASTRIDE + k + tig + 4]);
            }
            uint32_t bfr[8][2];
            #pragma unroll
            for (int ni = 0; ni < 8; ni++) {
                int n = warpN * 64 + ni * 8 + g;
                bfr[ni][0] = __float_as_uint(Bkc[n * G1_BSTRIDE + k + tig]);
                bfr[ni][1] = __float_as_uint(Bkc[n * G1_BSTRIDE + k + tig + 4]);
            }
            #pragma unroll
            for (int mi = 0; mi < 2; mi++)
                #pragma unroll
                for (int ni = 0; ni < 8; ni++)
                    mma_tf32(acc[mi][ni], afr[mi], bfr[ni]);
        }
    }

    // ---- epilogue: bias + store + fused BN column stats ----
    #pragma unroll
    for (int ni = 0; ni < 8; ni++) {
        int col = warpN * 64 + ni * 8 + tig * 2;
        float b0 = bias[col], b1 = bias[col + 1];
        float s0 = 0.f, q0 = 0.f, s1 = 0.f, q1 = 0.f;
        #pragma unroll
        for (int mi = 0; mi < 2; mi++) {
            int r0 = m0 + warpM * 32 + mi * 16 + g;
            if (r0 < M) {
                float v0 = acc[mi][ni][0] + b0;
                float v1 = acc[mi][ni][1] + b1;
                *reinterpret_cast<float2*>(&C[(size_t)r0 * 128 + col]) = make_float2(v0, v1);
                s0 += v0; q0 += v0 * v0; s1 += v1; q1 += v1 * v1;
            }
            int r1 = r0 + 8;
            if (r1 < M) {
                float v2 = acc[mi][ni][2] + b0;
                float v3 = acc[mi][ni][3] + b1;
                *reinterpret_cast<float2*>(&C[(size_t)r1 * 128 + col]) = make_float2(v2, v3);
                s0 += v2; q0 += v2 * v2; s1 += v3; q1 += v3 * v3;
            }
        }
        atomicAdd(&ssum[col], s0); atomicAdd(&ssq[col], q0);
        atomicAdd(&ssum[col + 1], s1); atomicAdd(&ssq[col + 1], q1);
    }
    __syncthreads();
    if (tid < 128) {
        atomicAdd(&g_colsum[tid], ssum[tid]);
        atomicAdd(&g_colsumsq[tid], ssq[tid]);
    }
}

// ---------------- BN finalize ----------------
__global__ void bn_finalize_kernel(float invM, const float* __restrict__ gamma,
                                   const float* __restrict__ beta) {
    int j = threadIdx.x;
    float mean = g_colsum[j] * invM;
    float var = g_colsumsq[j] * invM - mean * mean;
    float sc = gamma[j] * rsqrtf(var + 1e-5f);
    g_scale[j] = sc;
    g_shift[j] = beta[j] - mean * sc;
}

// ---------------- SIMT fp32 GEMM for layer 2 (N=32), BN affine+ReLU fused on A1 ----------------
template <int BM, int BN, int BK, int TM, int TN>
__launch_bounds__((BM / TM) * (BN / TN))
__global__ void gemm2_kernel(const float* __restrict__ A0, const float* __restrict__ A1,
                             const float* __restrict__ B, const float* __restrict__ bias,
                             float* __restrict__ C, int M, int N) {
    constexpr int K = 256, K0 = 128;
    constexpr int THREADS = (BM / TM) * (BN / TN);
    constexpr int ASTRIDE = BM + 4;
    __shared__ float As[BK][ASTRIDE];
    __shared__ float Bs[BK][BN];
    int tid = threadIdx.x;
    int m0 = blockIdx.x * BM;
    int n0 = blockIdx.y * BN;
    int tcol = tid % (BN / TN);
    int trow = tid / (BN / TN);

    float acc[TM][TN];
    #pragma unroll
    for (int i = 0; i < TM; i++)
        #pragma unroll
        for (int j = 0; j < TN; j++) acc[i][j] = 0.f;

    #pragma unroll 1
    for (int k0 = 0; k0 < K; k0 += BK) {
        #pragma unroll
        for (int idx = tid; idx < BM * BK / 4; idx += THREADS) {
            int m  = idx / (BK / 4);
            int kq = (idx % (BK / 4)) * 4;
            int row = m0 + m;
            int k = k0 + kq;
            float4 v = make_float4(0.f, 0.f, 0.f, 0.f);
            if (row < M) {
                if (k < K0) {
                    v = *reinterpret_cast<const float4*>(A0 + (size_t)row * K0 + k);
                } else {
                    int c = k - K0;
                    v = *reinterpret_cast<const float4*>(A1 + (size_t)row * K0 + c);
                    v.x = fmaxf(fmaf(v.x, g_scale[c + 0], g_shift[c + 0]), 0.f);
                    v.y = fmaxf(fmaf(v.y, g_scale[c + 1], g_shift[c + 1]), 0.f);
                    v.z = fmaxf(fmaf(v.z, g_scale[c + 2], g_shift[c + 2]), 0.f);
                    v.w = fmaxf(fmaf(v.w, g_scale[c + 3], g_shift[c + 3]), 0.f);
                }
            }
            As[kq + 0][m] = v.x; As[kq + 1][m] = v.y;
            As[kq + 2][m] = v.z; As[kq + 3][m] = v.w;
        }
        #pragma unroll
        for (int idx = tid; idx < BK * BN / 4; idx += THREADS) {
            int kr = idx / (BN / 4);
            int nq = (idx % (BN / 4)) * 4;
            float4 v = *reinterpret_cast<const float4*>(B + (size_t)(k0 + kr) * N + n0 + nq);
            *reinterpret_cast<float4*>(&Bs[kr][nq]) = v;
        }
        __syncthreads();
        #pragma unroll
        for (int kk = 0; kk < BK; kk++) {
            float ra[TM], rb[TN];
            #pragma unroll
            for (int i = 0; i < TM; i += 4) {
                float4 a = *reinterpret_cast<const float4*>(&As[kk][trow * TM + i]);
                ra[i] = a.x; ra[i + 1] = a.y; ra[i + 2] = a.z; ra[i + 3] = a.w;
            }
            #pragma unroll
            for (int j = 0; j < TN; j += 4) {
                float4 b = *reinterpret_cast<const float4*>(&Bs[kk][tcol * TN + j]);
                rb[j] = b.x; rb[j + 1] = b.y; rb[j + 2] = b.z; rb[j + 3] = b.w;
            }
            #pragma unroll
            for (int i = 0; i < TM; i++)
                #pragma unroll
                for (int j = 0; j < TN; j++) acc[i][j] += ra[i] * rb[j];
        }
        __syncthreads();
    }
    #pragma unroll
    for (int i = 0; i < TM; i++) {
        int row = m0 + trow * TM + i;
        if (row >= M) continue;
        #pragma unroll
        for (int j = 0; j < TN; j++) {
            int cn = n0 + tcol * TN + j;
            C[(size_t)row * N + cn] = acc[i][j] + bias[cn];
        }
    }
}

// ---------------- launch ----------------
extern "C" void kernel_launch(void* const* d_in, const int* in_sizes, int n_in,
                              void* d_out, int out_size) {
    const float* x     = (const float*)d_in[0];
    const int*   ei    = (const int*)d_in[1];
    const float* Wl1   = (const float*)d_in[2];
    const float* bl1   = (const float*)d_in[3];
    const float* Wr1   = (const float*)d_in[4];
    const float* gamma = (const float*)d_in[5];
    const float* beta  = (const float*)d_in[6];
    const float* Wl2   = (const float*)d_in[7];
    const float* bl2   = (const float*)d_in[8];
    const float* Wr2   = (const float*)d_in[9];
    float* out = (float*)d_out;

    int M = in_sizes[0] / D_IN;       // 50000
    int E = in_sizes[1] / 2;          // 800000
    const int* src = ei;
    const int* dst = ei + E;

    float *p_agg, *p_h, *p_B1t, *p_B2;
    cudaGetSymbolAddress((void**)&p_agg, g_agg);
    cudaGetSymbolAddress((void**)&p_h,   g_h);
    cudaGetSymbolAddress((void**)&p_B1t, g_B1t);
    cudaGetSymbolAddress((void**)&p_B2,  g_B2);

    cudaFuncSetAttribute(gemm1_mma_kernel,
                         cudaFuncAttributeMaxDynamicSharedMemorySize, G1_SMEM_BYTES);

    // setup + CSR build
    setup_kernel<<<(N_NODES + 255) / 256, 256>>>(Wl1, Wr1, Wl2, Wr2);
    hist_kernel<<<(E + 255) / 256, 256>>>(dst, E);
    scan_kernel<<<1, 1024>>>(M);
    scatter_kernel<<<(E + 255) / 256, 256>>>(src, dst, E);

    // layer 1: agg = scatter_max(x); h = [agg|x] @ B1 + b1 (tf32 mma, fused BN stats)
    agg_max_kernel<false><<<(M * 32 + 255) / 256, 256>>>(x, p_agg, M);
    gemm1_mma_kernel<<<(M + 127) / 128, 256, G1_SMEM_BYTES>>>(p_agg, x, p_B1t, bl1, p_h, M);
    bn_finalize_kernel<<<1, D_H>>>(1.0f / (float)M, gamma, beta);

    // layer 2: agg2 = scatter_max(relu(bn(h))); out = [agg2 | relu(bn(h))] @ B2 + b2 (exact fp32)
    agg_max_kernel<true><<<(M * 32 + 255) / 256, 256>>>(p_h, p_agg, M);
    {
        dim3 grid((M + 127) / 128, D_OUT / 32);
        gemm2_kernel<128, 32, 16, 8, 4><<<grid, 128>>>(p_agg, p_h, p_B2, bl2, out, M, D_OUT);
    }
}

// round 8
// speedup vs baseline: 1.6127x; 1.0924x over previous
#include <cuda_runtime.h>
#include <cuda_bf16.h>
#include <cuda_fp16.h>
#include <math_constants.h>
#include <cstdint>

#define N_NODES 50000
#define N_EDGES 800000
#define D_IN 128
#define D_H 128
#define D_OUT 32

// ---------------- scratch (device globals; no allocation allowed) ----------------
__device__ int    g_cnt[N_NODES];
__device__ int    g_row_ptr[N_NODES + 1];
__device__ int    g_rank[N_EDGES];
__device__ int    g_col[N_EDGES];
__device__ float  g_agg[(size_t)N_NODES * D_H];
__device__ float  g_h[(size_t)N_NODES * D_H];
__device__ __half g_x16[(size_t)N_NODES * D_H];
__device__ __half g_h16[(size_t)N_NODES * D_H];
__device__ float  g_B1t[128 * 256];   // layer-1 weights [N=128][K=256] K-major, tf32-rounded
__device__ float  g_B2t[32 * 256];    // layer-2 weights [N=32][K=256]  K-major, tf32-rounded
__device__ float  g_colsum[D_H];
__device__ float  g_colsumsq[D_H];

__device__ __forceinline__ float f2tf32(float x) {
    float r;
    asm("cvt.rna.tf32.f32 %0, %1;" : "=f"(r) : "f"(x));
    return r;
}

// ---------------- setup: zero counters/stats + prepack both weight blocks ----------------
__global__ void setup_kernel(const float* __restrict__ Wl1, const float* __restrict__ Wr1,
                             const float* __restrict__ Wl2, const float* __restrict__ Wr2) {
    int i = blockIdx.x * blockDim.x + threadIdx.x;
    if (i < N_NODES) g_cnt[i] = 0;
    if (i < D_H) { g_colsum[i] = 0.f; g_colsumsq[i] = 0.f; }
    if (i < 128 * 256) {
        int n = i / 256, k = i % 256;
        float v = (k < 128) ? Wl1[n * 128 + k] : Wr1[n * 128 + (k - 128)];
        g_B1t[i] = f2tf32(v);
    }
    if (i < 32 * 256) {
        int n = i / 256, k = i % 256;
        float v = (k < 128) ? Wl2[n * 128 + k] : Wr2[n * 128 + (k - 128)];
        g_B2t[i] = f2tf32(v);
    }
}

// ---------------- CSR build ----------------
// histogram + per-edge rank; also converts x -> fp16 (independent work, fused)
__global__ void hist_kernel(const int* __restrict__ dst, int E,
                            const float* __restrict__ x, int total4) {
    int e = blockIdx.x * blockDim.x + threadIdx.x;
    if (e < E) g_rank[e] = atomicAdd(&g_cnt[dst[e]], 1);
    const float4* X4 = reinterpret_cast<const float4*>(x);
    for (int idx = e; idx < total4; idx += E) {
        float4 v = __ldg(&X4[idx]);
        __half2 a = __floats2half2_rn(v.x, v.y);
        __half2 b = __floats2half2_rn(v.z, v.w);
        uint2 o;
        o.x = *reinterpret_cast<uint32_t*>(&a);
        o.y = *reinterpret_cast<uint32_t*>(&b);
        *reinterpret_cast<uint2*>(&g_x16[(size_t)idx * 4]) = o;
    }
}

__global__ void scan_kernel(int n) {
    __shared__ int s[1024];
    const int PER = (n + 1023) / 1024;
    int t = threadIdx.x;
    int start = t * PER;
    int end = min(start + PER, n);
    int sum = 0;
    for (int i = start; i < end; i++) sum += g_cnt[i];
    s[t] = sum;
    __syncthreads();
    #pragma unroll
    for (int d = 1; d < 1024; d <<= 1) {
        int u = (t >= d) ? s[t - d] : 0;
        __syncthreads();
        s[t] += u;
        __syncthreads();
    }
    int run = s[t] - sum;
    for (int i = start; i < end; i++) {
        int c = g_cnt[i];
        g_row_ptr[i] = run;
        run += c;
    }
    if (t == 1023) g_row_ptr[n] = run;
}

__global__ void scatter_kernel(const int* __restrict__ src, const int* __restrict__ dst, int E) {
    int e = blockIdx.x * blockDim.x + threadIdx.x;
    if (e < E) {
        int d = dst[e];
        g_col[g_row_ptr[d] + g_rank[e]] = src[e];
    }
}

// ---------------- scatter-max aggregation over fp16 source: one warp per node ----------------
// XFORM: compute BN scale/shift per block, apply affine+ReLU to gathered elems before max
template <bool XFORM>
__global__ void agg16_kernel(const __half* __restrict__ X16, float* __restrict__ AGG, int nNodes,
                             const float* __restrict__ gamma, const float* __restrict__ beta,
                             float invM) {
    __shared__ float s_sc[XFORM ? 128 : 1];
    __shared__ float s_sh[XFORM ? 128 : 1];
    int tid = threadIdx.x;
    if (XFORM) {
        if (tid < 128) {
            float mean = g_colsum[tid] * invM;
            float var = g_colsumsq[tid] * invM - mean * mean;
            float sc = gamma[tid] * rsqrtf(var + 1e-5f);
            s_sc[tid] = sc;
            s_sh[tid] = beta[tid] - mean * sc;
        }
        __syncthreads();
    }
    int warp = (blockIdx.x * blockDim.x + tid) >> 5;
    int lane = tid & 31;
    if (warp >= nNodes) return;
    int s = g_row_ptr[warp];
    int e = g_row_ptr[warp + 1];
    float4 sc, sh;
    if (XFORM) {
        sc = *reinterpret_cast<const float4*>(&s_sc[lane * 4]);
        sh = *reinterpret_cast<const float4*>(&s_sh[lane * 4]);
    }
    float4 m = make_float4(-CUDART_INF_F, -CUDART_INF_F, -CUDART_INF_F, -CUDART_INF_F);
    const uint2* X2 = reinterpret_cast<const uint2*>(X16);
    #pragma unroll 4
    for (int i = s; i < e; i++) {
        int src = __ldg(&g_col[i]);
        uint2 p = __ldg(&X2[(size_t)src * 32 + lane]);
        __half2 h0 = *reinterpret_cast<const __half2*>(&p.x);
        __half2 h1 = *reinterpret_cast<const __half2*>(&p.y);
        float2 f0 = __half22float2(h0);
        float2 f1 = __half22float2(h1);
        if (XFORM) {
            f0.x = fmaxf(fmaf(f0.x, sc.x, sh.x), 0.f);
            f0.y = fmaxf(fmaf(f0.y, sc.y, sh.y), 0.f);
            f1.x = fmaxf(fmaf(f1.x, sc.z, sh.z), 0.f);
            f1.y = fmaxf(fmaf(f1.y, sc.w, sh.w), 0.f);
        }
        m.x = fmaxf(m.x, f0.x); m.y = fmaxf(m.y, f0.y);
        m.z = fmaxf(m.z, f1.x); m.w = fmaxf(m.w, f1.y);
    }
    if (s == e) m = make_float4(0.f, 0.f, 0.f, 0.f);
    reinterpret_cast<float4*>(AGG)[(size_t)warp * 32 + lane] = m;
}

// ---------------- common mma helper ----------------
__device__ __forceinline__ void mma_tf32(float* d, const uint32_t* a, const uint32_t* b) {
    asm volatile(
        "mma.sync.aligned.m16n8k8.row.col.f32.tf32.tf32.f32 "
        "{%0,%1,%2,%3}, {%4,%5,%6,%7}, {%8,%9}, {%0,%1,%2,%3};"
        : "+f"(d[0]), "+f"(d[1]), "+f"(d[2]), "+f"(d[3])
        : "r"(a[0]), "r"(a[1]), "r"(a[2]), "r"(a[3]), "r"(b[0]), "r"(b[1]));
}

// ---------------- layer-1 GEMM via mma.sync tf32 ----------------
// C[M,128] = [A0 | A1] @ B1t^T + bias; fused BN column stats; also writes h in fp16.
#define G1_BSTRIDE 260
#define G1_ASTRIDE 68
#define G1_SMEM_BYTES ((128 * G1_BSTRIDE + 128 * G1_ASTRIDE + 256) * 4)

__global__ __launch_bounds__(256, 1)
void gemm1_mma_kernel(const float* __restrict__ A0, const float* __restrict__ A1,
                      const float* __restrict__ Bt, const float* __restrict__ bias,
                      float* __restrict__ C, int M) {
    extern __shared__ float sm[];
    float* Bs   = sm;                       // [128][260]
    float* As   = sm + 128 * G1_BSTRIDE;    // [128][68]
    float* ssum = As + 128 * G1_ASTRIDE;    // [128]
    float* ssq  = ssum + 128;               // [128]

    int tid = threadIdx.x;
    int lane = tid & 31;
    int wid = tid >> 5;
    int warpM = wid & 3;
    int warpN = wid >> 2;
    int g = lane >> 2;
    int tig = lane & 3;
    int m0 = blockIdx.x * 128;

    if (tid < 128) { ssum[tid] = 0.f; ssq[tid] = 0.f; }

    const float4* Bt4 = reinterpret_cast<const float4*>(Bt);
    #pragma unroll 8
    for (int idx = tid; idx < 128 * 64; idx += 256) {
        int n = idx >> 6, k4 = idx & 63;
        float4 v = __ldg(&Bt4[n * 64 + k4]);
        *reinterpret_cast<float4*>(&Bs[n * G1_BSTRIDE + k4 * 4]) = v;
    }

    float acc[2][8][4];
    #pragma unroll
    for (int mi = 0; mi < 2; mi++)
        #pragma unroll
        for (int ni = 0; ni < 8; ni++)
            #pragma unroll
            for (int q = 0; q < 4; q++) acc[mi][ni][q] = 0.f;

    float4 stage[8];
    {
        const float4* S4 = reinterpret_cast<const float4*>(A0);
        #pragma unroll
        for (int j = 0; j < 8; j++) {
            int i = tid + 256 * j;
            int r = i >> 4, c4 = i & 15;
            int row = m0 + r;
            stage[j] = (row < M) ? __ldg(&S4[(size_t)row * 32 + c4])
                                 : make_float4(0.f, 0.f, 0.f, 0.f);
        }
    }

    #pragma unroll 1
    for (int kc = 0; kc < 4; kc++) {
        __syncthreads();
        #pragma unroll
        for (int j = 0; j < 8; j++) {
            int i = tid + 256 * j;
            int r = i >> 4, c4 = i & 15;
            float4 v = stage[j];
            v.x = f2tf32(v.x); v.y = f2tf32(v.y); v.z = f2tf32(v.z); v.w = f2tf32(v.w);
            *reinterpret_cast<float4*>(&As[r * G1_ASTRIDE + c4 * 4]) = v;
        }
        if (kc < 3) {
            int nc = kc + 1;
            const float4* S4 = reinterpret_cast<const float4*>(nc < 2 ? A0 : A1);
            int cbase = (nc & 1) * 16;
            #pragma unroll
            for (int j = 0; j < 8; j++) {
                int i = tid + 256 * j;
                int r = i >> 4, c4 = i & 15;
                int row = m0 + r;
                stage[j] = (row < M) ? __ldg(&S4[(size_t)row * 32 + cbase + c4])
                                     : make_float4(0.f, 0.f, 0.f, 0.f);
            }
        }
        __syncthreads();

        const float* Bkc = Bs + kc * 64;
        #pragma unroll
        for (int ks = 0; ks < 8; ks++) {
            int k = ks * 8;
            uint32_t afr[2][4];
            #pragma unroll
            for (int mi = 0; mi < 2; mi++) {
                int r = warpM * 32 + mi * 16 + g;
                afr[mi][0] = __float_as_uint(As[r * G1_ASTRIDE + k + tig]);
                afr[mi][1] = __float_as_uint(As[(r + 8) * G1_ASTRIDE + k + tig]);
                afr[mi][2] = __float_as_uint(As[r * G1_ASTRIDE + k + tig + 4]);
                afr[mi][3] = __float_as_uint(As[(r + 8) * G1_ASTRIDE + k + tig + 4]);
            }
            uint32_t bfr[8][2];
            #pragma unroll
            for (int ni = 0; ni < 8; ni++) {
                int n = warpN * 64 + ni * 8 + g;
                bfr[ni][0] = __float_as_uint(Bkc[n * G1_BSTRIDE + k + tig]);
                bfr[ni][1] = __float_as_uint(Bkc[n * G1_BSTRIDE + k + tig + 4]);
            }
            #pragma unroll
            for (int mi = 0; mi < 2; mi++)
                #pragma unroll
                for (int ni = 0; ni < 8; ni++)
                    mma_tf32(acc[mi][ni], afr[mi], bfr[ni]);
        }
    }

    // epilogue: bias + store fp32 & fp16 + fused BN column stats
    #pragma unroll
    for (int ni = 0; ni < 8; ni++) {
        int col = warpN * 64 + ni * 8 + tig * 2;
        float b0 = bias[col], b1 = bias[col + 1];
        float s0 = 0.f, q0 = 0.f, s1 = 0.f, q1 = 0.f;
        #pragma unroll
        for (int mi = 0; mi < 2; mi++) {
            int r0 = m0 + warpM * 32 + mi * 16 + g;
            if (r0 < M) {
                float v0 = acc[mi][ni][0] + b0;
                float v1 = acc[mi][ni][1] + b1;
                *reinterpret_cast<float2*>(&C[(size_t)r0 * 128 + col]) = make_float2(v0, v1);
                __half2 hh = __floats2half2_rn(v0, v1);
                *reinterpret_cast<uint32_t*>(&g_h16[(size_t)r0 * 128 + col]) =
                    *reinterpret_cast<uint32_t*>(&hh);
                s0 += v0; q0 += v0 * v0; s1 += v1; q1 += v1 * v1;
            }
            int r1 = r0 + 8;
            if (r1 < M) {
                float v2 = acc[mi][ni][2] + b0;
                float v3 = acc[mi][ni][3] + b1;
                *reinterpret_cast<float2*>(&C[(size_t)r1 * 128 + col]) = make_float2(v2, v3);
                __half2 hh = __floats2half2_rn(v2, v3);
                *reinterpret_cast<uint32_t*>(&g_h16[(size_t)r1 * 128 + col]) =
                    *reinterpret_cast<uint32_t*>(&hh);
                s0 += v2; q0 += v2 * v2; s1 += v3; q1 += v3 * v3;
            }
        }
        atomicAdd(&ssum[col], s0); atomicAdd(&ssq[col], q0);
        atomicAdd(&ssum[col + 1], s1); atomicAdd(&ssq[col + 1], q1);
    }
    __syncthreads();
    if (tid < 128) {
        atomicAdd(&g_colsum[tid], ssum[tid]);
        atomicAdd(&g_colsumsq[tid], ssq[tid]);
    }
}

// ---------------- layer-2 GEMM via mma.sync tf32 (N=32) ----------------
// out[M,32] = [A0 | relu(bn(A1))] @ B2t^T + bias. BN scale/shift computed per block.
#define G2_BSTRIDE 260
#define G2_ASTRIDE 68
#define G2_SMEM_BYTES ((32 * G2_BSTRIDE + 128 * G2_ASTRIDE + 256) * 4)

__global__ __launch_bounds__(256)
void gemm2_mma_kernel(const float* __restrict__ A0, const float* __restrict__ A1,
                      const float* __restrict__ Bt, const float* __restrict__ bias,
                      const float* __restrict__ gamma, const float* __restrict__ beta,
                      float invM, float* __restrict__ C, int M) {
    extern __shared__ float sm[];
    float* Bs   = sm;                      // [32][260]
    float* As   = sm + 32 * G2_BSTRIDE;    // [128][68]
    float* s_sc = As + 128 * G2_ASTRIDE;   // [128]
    float* s_sh = s_sc + 128;              // [128]

    int tid = threadIdx.x;
    int lane = tid & 31;
    int wid = tid >> 5;        // 0..7 -> 16-row slabs
    int g = lane >> 2;
    int tig = lane & 3;
    int m0 = blockIdx.x * 128;

    if (tid < 128) {
        float mean = g_colsum[tid] * invM;
        float var = g_colsumsq[tid] * invM - mean * mean;
        float sc = gamma[tid] * rsqrtf(var + 1e-5f);
        s_sc[tid] = sc;
        s_sh[tid] = beta[tid] - mean * sc;
    }

    const float4* Bt4 = reinterpret_cast<const float4*>(Bt);
    #pragma unroll
    for (int idx = tid; idx < 32 * 64; idx += 256) {
        int n = idx >> 6, k4 = idx & 63;
        float4 v = __ldg(&Bt4[n * 64 + k4]);
        *reinterpret_cast<float4*>(&Bs[n * G2_BSTRIDE + k4 * 4]) = v;
    }

    float acc[4][4];
    #pragma unroll
    for (int ni = 0; ni < 4; ni++)
        #pragma unroll
        for (int q = 0; q < 4; q++) acc[ni][q] = 0.f;

    float4 stage[8];
    {
        const float4* S4 = reinterpret_cast<const float4*>(A0);
        #pragma unroll
        for (int j = 0; j < 8; j++) {
            int i = tid + 256 * j;
            int r = i >> 4, c4 = i & 15;
            int row = m0 + r;
            stage[j] = (row < M) ? __ldg(&S4[(size_t)row * 32 + c4])
                                 : make_float4(0.f, 0.f, 0.f, 0.f);
        }
    }

    #pragma unroll 1
    for (int kc = 0; kc < 4; kc++) {
        __syncthreads();  // also orders s_sc/s_sh on first iteration
        #pragma unroll
        for (int j = 0; j < 8; j++) {
            int i = tid + 256 * j;
            int r = i >> 4, c4 = i & 15;
            float4 v = stage[j];
            if (kc >= 2) {  // A1 half: BN affine + ReLU
                int cb = (kc & 1) * 64 + c4 * 4;
                v.x = fmaxf(fmaf(v.x, s_sc[cb + 0], s_sh[cb + 0]), 0.f);
                v.y = fmaxf(fmaf(v.y, s_sc[cb + 1], s_sh[cb + 1]), 0.f);
                v.z = fmaxf(fmaf(v.z, s_sc[cb + 2], s_sh[cb + 2]), 0.f);
                v.w = fmaxf(fmaf(v.w, s_sc[cb + 3], s_sh[cb + 3]), 0.f);
            }
            v.x = f2tf32(v.x); v.y = f2tf32(v.y); v.z = f2tf32(v.z); v.w = f2tf32(v.w);
            *reinterpret_cast<float4*>(&As[r * G2_ASTRIDE + c4 * 4]) = v;
        }
        if (kc < 3) {
            int nc = kc + 1;
            const float4* S4 = reinterpret_cast<const float4*>(nc < 2 ? A0 : A1);
            int cbase = (nc & 1) * 16;
            #pragma unroll
            for (int j = 0; j < 8; j++) {
                int i = tid + 256 * j;
                int r = i >> 4, c4 = i & 15;
                int row = m0 + r;
                stage[j] = (row < M) ? __ldg(&S4[(size_t)row * 32 + cbase + c4])
                                     : make_float4(0.f, 0.f, 0.f, 0.f);
            }
        }
        __syncthreads();

        const float* Bkc = Bs + kc * 64;
        #pragma unroll
        for (int ks = 0; ks < 8; ks++) {
            int k = ks * 8;
            uint32_t afr[4];
            int r = wid * 16 + g;
            afr[0] = __float_as_uint(As[r * G2_ASTRIDE + k + tig]);
            afr[1] = __float_as_uint(As[(r + 8) * G2_ASTRIDE + k + tig]);
            afr[2] = __float_as_uint(As[r * G2_ASTRIDE + k + tig + 4]);
            afr[3] = __float_as_uint(As[(r + 8) * G2_ASTRIDE + k + tig + 4]);
            uint32_t bfr[4][2];
            #pragma unroll
            for (int ni = 0; ni < 4; ni++) {
                int n = ni * 8 + g;
                bfr[ni][0] = __float_as_uint(Bkc[n * G2_BSTRIDE + k + tig]);
                bfr[ni][1] = __float_as_uint(Bkc[n * G2_BSTRIDE + k + tig + 4]);
            }
            #pragma unroll
            for (int ni = 0; ni < 4; ni++)
                mma_tf32(acc[ni], afr, bfr[ni]);
        }
    }

    #pragma unroll
    for (int ni = 0; ni < 4; ni++) {
        int col = ni * 8 + tig * 2;
        float b0 = bias[col], b1 = bias[col + 1];
        int r0 = m0 + wid * 16 + g;
        if (r0 < M)
            *reinterpret_cast<float2*>(&C[(size_t)r0 * 32 + col]) =
                make_float2(acc[ni][0] + b0, acc[ni][1] + b1);
        int r1 = r0 + 8;
        if (r1 < M)
            *reinterpret_cast<float2*>(&C[(size_t)r1 * 32 + col]) =
                make_float2(acc[ni][2] + b0, acc[ni][3] + b1);
    }
}

// ---------------- launch ----------------
extern "C" void kernel_launch(void* const* d_in, const int* in_sizes, int n_in,
                              void* d_out, int out_size) {
    const float* x     = (const float*)d_in[0];
    const int*   ei    = (const int*)d_in[1];
    const float* Wl1   = (const float*)d_in[2];
    const float* bl1   = (const float*)d_in[3];
    const float* Wr1   = (const float*)d_in[4];
    const float* gamma = (const float*)d_in[5];
    const float* beta  = (const float*)d_in[6];
    const float* Wl2   = (const float*)d_in[7];
    const float* bl2   = (const float*)d_in[8];
    const float* Wr2   = (const float*)d_in[9];
    float* out = (float*)d_out;

    int M = in_sizes[0] / D_IN;       // 50000
    int E = in_sizes[1] / 2;          // 800000
    const int* src = ei;
    const int* dst = ei + E;
    float invM = 1.0f / (float)M;

    float *p_agg, *p_h, *p_B1t, *p_B2t;
    __half *p_x16, *p_h16;
    cudaGetSymbolAddress((void**)&p_agg,  g_agg);
    cudaGetSymbolAddress((void**)&p_h,    g_h);
    cudaGetSymbolAddress((void**)&p_B1t,  g_B1t);
    cudaGetSymbolAddress((void**)&p_B2t,  g_B2t);
    cudaGetSymbolAddress((void**)&p_x16,  g_x16);
    cudaGetSymbolAddress((void**)&p_h16,  g_h16);

    cudaFuncSetAttribute(gemm1_mma_kernel,
                         cudaFuncAttributeMaxDynamicSharedMemorySize, G1_SMEM_BYTES);
    cudaFuncSetAttribute(gemm2_mma_kernel,
                         cudaFuncAttributeMaxDynamicSharedMemorySize, G2_SMEM_BYTES);

    // setup + CSR build (hist also converts x -> fp16)
    setup_kernel<<<(N_NODES + 255) / 256, 256>>>(Wl1, Wr1, Wl2, Wr2);
    hist_kernel<<<(E + 255) / 256, 256>>>(dst, E, x, M * 32);
    scan_kernel<<<1, 1024>>>(M);
    scatter_kernel<<<(E + 255) / 256, 256>>>(src, dst, E);

    // layer 1: agg = scatter_max(x16); h = [agg|x] @ B1 + b1 (tf32 mma, fused stats, h16 out)
    agg16_kernel<false><<<(M * 32 + 255) / 256, 256>>>(p_x16, p_agg, M, gamma, beta, invM);
    gemm1_mma_kernel<<<(M + 127) / 128, 256, G1_SMEM_BYTES>>>(p_agg, x, p_B1t, bl1, p_h, M);

    // layer 2: agg2 = scatter_max(relu(bn(h16))); out = [agg2 | relu(bn(h))] @ B2 + b2
    agg16_kernel<true><<<(M * 32 + 255) / 256, 256>>>(p_h16, p_agg, M, gamma, beta, invM);
    gemm2_mma_kernel<<<(M + 127) / 128, 256, G2_SMEM_BYTES>>>(p_agg, p_h, p_B2t, bl2,
                                                              gamma, beta, invM, out, M);
}